// round 14
// baseline (speedup 1.0000x reference)
#include <cuda_runtime.h>
#include <cuda_bf16.h>
#include <cstdint>

typedef __nv_bfloat16 bf16;
typedef __nv_bfloat162 bf162;

#define B_ 4
#define C_ 512
#define M_ 512
#define H_ 8
#define F_ 2048
#define L_ 6
#define T_ 32000
#define R_ 2048
#define RM (R_ * M_)

// ---------------- scratch ----------------
__device__ float g_x[RM];
__device__ bf16  g_xh[RM],  g_xl[RM];
__device__ bf16  g_ench[RM], g_encl[RM];
__device__ bf16  g_qh[RM],  g_ql[RM];
__device__ bf16  g_kh[RM],  g_kl[RM];
__device__ bf16  g_vth[RM], g_vtl[RM];             // (b,h,v,c)
__device__ bf16  g_ckh[L_*RM], g_ckl[L_*RM];       // per-layer cross K
__device__ bf16  g_cvth[L_*RM], g_cvtl[L_*RM];     // per-layer cross vT
__device__ bf16  g_preh[RM], g_prel[RM];
__device__ bf16  g_ffh[R_ * F_],  g_ffl[R_ * F_];
__device__ float g_tmp[RM];
__device__ bf16 g_wqkv_h[L_*2*3*M_*M_], g_wqkv_l[L_*2*3*M_*M_];
__device__ bf16 g_wot_h[L_*2*M_*M_], g_wot_l[L_*2*M_*M_];
__device__ bf16 g_w1t_h[L_*F_*M_],   g_w1t_l[L_*F_*M_];
__device__ bf16 g_w2t_h[L_*M_*F_],   g_w2t_l[L_*M_*F_];
__device__ bf16 g_wft_h[(size_t)T_*M_], g_wft_l[(size_t)T_*M_];

// ---------------- helpers ----------------
__device__ __forceinline__ uint32_t smem_u32(const void* p) {
    uint32_t a;
    asm("{ .reg .u64 t; cvta.to.shared.u64 t, %1; cvt.u32.u64 %0, t; }" : "=r"(a) : "l"(p));
    return a;
}
__device__ __forceinline__ void cpa16(uint32_t dst, const void* src) {
    asm volatile("cp.async.cg.shared.global [%0], [%1], 16;" :: "r"(dst), "l"(src));
}
__device__ __forceinline__ void ldm_x4(uint32_t* r, uint32_t addr) {
    asm volatile("ldmatrix.sync.aligned.m8n8.x4.shared.b16 {%0,%1,%2,%3}, [%4];"
                 : "=r"(r[0]), "=r"(r[1]), "=r"(r[2]), "=r"(r[3]) : "r"(addr));
}
__device__ __forceinline__ void mma_bf16(float* c, const uint32_t* a, uint32_t b0, uint32_t b1) {
    asm volatile("mma.sync.aligned.m16n8k16.row.col.f32.bf16.bf16.f32 "
                 "{%0,%1,%2,%3}, {%4,%5,%6,%7}, {%8,%9}, {%0,%1,%2,%3};"
                 : "+f"(c[0]), "+f"(c[1]), "+f"(c[2]), "+f"(c[3])
                 : "r"(a[0]), "r"(a[1]), "r"(a[2]), "r"(a[3]), "r"(b0), "r"(b1));
}
__device__ __forceinline__ void hilo(float v, bf16& h, bf16& l) {
    h = __float2bfloat16(v);
    l = __float2bfloat16(v - __bfloat162float(h));
}
__device__ __forceinline__ uint32_t pack2(bf16 a, bf16 b) {
    bf162 t{a, b};
    return *reinterpret_cast<uint32_t*>(&t);
}

// ---------------- split-bf16 tensor-core GEMM (mma.sync, NS-deep pipeline) ----------------
// EPI: 0 fp32 row-major; 1 hi/lo bf16 (layout per CB)
// CB:  0 plain  2 qkv-scatter  4 fused-qkv scatter  5 cross-KV scatter
template<int BN, int NS, int MINB, int EPI, int CB, bool BIAS, bool RELU>
__global__ __launch_bounds__(256, MINB) void tcmm(
    const bf16* __restrict__ Ah, const bf16* __restrict__ Al, int lda, long sA,
    const bf16* __restrict__ Bh, const bf16* __restrict__ Bl, int ldb, long sB,
    const float* __restrict__ bias,
    float* __restrict__ Cf, bf16* __restrict__ Ch, bf16* __restrict__ Cl,
    bf16* __restrict__ Dh, bf16* __restrict__ Dl,
    int ldc, long sC, int Kd, int nOfs, int swp)
{
    constexpr int WX = (BN == 128) ? 4 : 2;
    constexpr int WY = 8 / WX;
    constexpr int WM = 128 / WY;
    constexpr int WN = BN / WX;
    constexpr int MT = WM / 16;
    constexpr int NT = WN / 8;
    constexpr int RS = 80;
    constexpr int AS = 128 * RS;
    constexpr int BS = BN * RS;
    constexpr int STAGE = 2 * AS + 2 * BS;

    extern __shared__ char smem[];
    const uint32_t sb = smem_u32(smem);
    const int tid = threadIdx.x;
    const int z = blockIdx.z;
    int m0, n0;
    if (swp) { m0 = blockIdx.x * 128; n0 = blockIdx.y * BN; }
    else     { m0 = blockIdx.y * 128; n0 = blockIdx.x * BN; }
    const int lane = tid & 31, w = tid >> 5;
    const int wy = w % WY, wx = w / WY;

    const bf16* Abh = Ah + (long)z * sA;
    const bf16* Abl = Al + (long)z * sA;
    const bf16* Bbh = Bh + (long)z * sB;
    const bf16* Bbl = Bl + (long)z * sB;

    const int S = Kd >> 5;
    float acc[MT][NT][4] = {};

    auto loadStage = [&](int s) {
        const uint32_t buf = sb + (uint32_t)((NS == 4) ? (s & 3) : (s % 3)) * STAGE;
        const long k0 = (long)s << 5;
        for (int i = tid; i < 128 * 4; i += 256) {
            int row = i >> 2, ch = i & 3;
            uint32_t off = (uint32_t)(row * RS + ch * 16);
            long go = (long)(m0 + row) * lda + k0 + ch * 8;
            cpa16(buf + off, Abh + go);
            cpa16(buf + AS + off, Abl + go);
        }
        for (int i = tid; i < BN * 4; i += 256) {
            int row = i >> 2, ch = i & 3;
            uint32_t off = (uint32_t)(row * RS + ch * 16);
            long go = (long)(n0 + row) * ldb + k0 + ch * 8;
            cpa16(buf + 2 * AS + off, Bbh + go);
            cpa16(buf + 2 * AS + BS + off, Bbl + go);
        }
        asm volatile("cp.async.commit_group;" ::: "memory");
    };

    loadStage(0);
    if (S > 1) loadStage(1);
    if (NS == 4 && S > 2) loadStage(2);
    for (int s = 0; s < S; s++) {
        const int rem = S - 1 - s;
        if (NS == 4) {
            if (rem >= 2)      asm volatile("cp.async.wait_group 2;" ::: "memory");
            else if (rem == 1) asm volatile("cp.async.wait_group 1;" ::: "memory");
            else               asm volatile("cp.async.wait_group 0;" ::: "memory");
        } else {
            if (rem >= 1)      asm volatile("cp.async.wait_group 1;" ::: "memory");
            else               asm volatile("cp.async.wait_group 0;" ::: "memory");
        }
        __syncthreads();
        if (s + NS - 1 < S) loadStage(s + NS - 1);
        const uint32_t buf = sb + (uint32_t)((NS == 4) ? (s & 3) : (s % 3)) * STAGE;
        const uint32_t aRowOff = (uint32_t)((wy * WM + (lane & 15)) * RS);
        const uint32_t bRowOff = (uint32_t)((wx * WN + (lane & 15)) * RS);
#pragma unroll
        for (int kk = 0; kk < 2; kk++) {
            const uint32_t kOff = (uint32_t)(kk * 32 + ((lane >> 4) * 16));
            uint32_t ah[MT][4], al[MT][4], bh[2][4], bl[2][4];
#pragma unroll
            for (int mt = 0; mt < MT; mt++) {
                uint32_t ad = buf + aRowOff + (uint32_t)(mt * 16 * RS) + kOff;
                ldm_x4(ah[mt], ad);
                ldm_x4(al[mt], ad + AS);
            }
#pragma unroll
            for (int np = 0; np < 2; np++) {
                uint32_t bd = buf + 2 * AS + bRowOff + (uint32_t)(np * 16 * RS) + kOff;
                ldm_x4(bh[np], bd);
                ldm_x4(bl[np], bd + BS);
            }
#pragma unroll
            for (int mt = 0; mt < MT; mt++) {
#pragma unroll
                for (int nt = 0; nt < NT; nt++) {
                    const int np = nt >> 1, sel = nt & 1;
                    mma_bf16(acc[mt][nt], ah[mt], bh[np][sel], bh[np][sel + 2]);
                    mma_bf16(acc[mt][nt], ah[mt], bl[np][sel], bl[np][sel + 2]);
                    mma_bf16(acc[mt][nt], al[mt], bh[np][sel], bh[np][sel + 2]);
                }
            }
        }
    }

    // epilogue
    const int rBase = m0 + wy * WM + (lane >> 2);
    const int cBase = n0 + wx * WN + (lane & 3) * 2;
#pragma unroll
    for (int mt = 0; mt < MT; mt++) {
#pragma unroll
        for (int nt = 0; nt < NT; nt++) {
#pragma unroll
            for (int half = 0; half < 2; half++) {
                const int r = rBase + mt * 16 + half * 8;
                const int c = cBase + nt * 8;
                float v0 = acc[mt][nt][half * 2];
                float v1 = acc[mt][nt][half * 2 + 1];
                if (BIAS) { v0 += bias[c]; v1 += bias[c + 1]; }
                if (RELU) { v0 = fmaxf(v0, 0.0f); v1 = fmaxf(v1, 0.0f); }
                if (EPI == 0) {
                    long idx = (long)z * sC + (long)r * ldc + c;
                    float2 o = {v0, v1};
                    *(float2*)(Cf + idx) = o;
                } else if (CB == 4) {
                    const int nn = c + nOfs;
                    bf16 h0, l0, h1, l1;
                    hilo(v0, h0, l0); hilo(v1, h1, l1);
                    if (nn < 1024) {
                        int kc = nn & 511;
                        long idx = ((long)(r >> 9) * 8 + (kc >> 6)) * 32768 + (long)(r & 511) * 64 + (kc & 63);
                        bf162 Hh{h0, h1}, Ll{l0, l1};
                        if (nn < 512) { *(bf162*)(g_qh + idx) = Hh; *(bf162*)(g_ql + idx) = Ll; }
                        else          { *(bf162*)(g_kh + idx) = Hh; *(bf162*)(g_kl + idx) = Ll; }
                    } else {
                        int vc = nn - 1024;
                        long i0 = ((long)(r >> 9) * 512 + vc) * 512 + (r & 511);
                        g_vth[i0] = h0; g_vtl[i0] = l0;
                        g_vth[i0 + 512] = h1; g_vtl[i0 + 512] = l1;
                    }
                } else if (CB == 5) {
                    const int nn = c + nOfs;
                    const long lofs = (long)z * RM;
                    bf16 h0, l0, h1, l1;
                    hilo(v0, h0, l0); hilo(v1, h1, l1);
                    if (nn < 1024) {
                        int kc = nn & 511;
                        long idx = lofs + ((long)(r >> 9) * 8 + (kc >> 6)) * 32768 + (long)(r & 511) * 64 + (kc & 63);
                        bf162 Hh{h0, h1}, Ll{l0, l1};
                        *(bf162*)(Ch + idx) = Hh; *(bf162*)(Cl + idx) = Ll;
                    } else {
                        int vc = nn - 1024;
                        long i0 = lofs + ((long)(r >> 9) * 512 + vc) * 512 + (r & 511);
                        Dh[i0] = h0; Dl[i0] = l0;
                        Dh[i0 + 512] = h1; Dl[i0 + 512] = l1;
                    }
                } else {
                    long idx;
                    if (CB == 0) idx = (long)z * sC + (long)r * ldc + c;
                    else         idx = (((long)(r >> 9) * 8 + (c >> 6)) << 15) + (long)(r & 511) * 64 + (c & 63);
                    bf16 h0, l0, h1, l1;
                    hilo(v0, h0, l0); hilo(v1, h1, l1);
                    bf162 Hh{h0, h1}, Ll{l0, l1};
                    *(bf162*)(Ch + idx) = Hh;
                    *(bf162*)(Cl + idx) = Ll;
                }
            }
        }
    }
}

// ---------------- fused flash attention (64-row Q tiles, 4 warps, 2 CTA/SM) ----------------
#define RSQ 144
#define RSV 272
#define FQH 0
#define FQL (64 * RSQ)              // 9216
#define FKH (2 * 64 * RSQ)          // 18432
#define KLOFS (128 * RSQ)           // 18432 (hi->lo offset within K)
#define FVH (FKH + 2 * 128 * RSQ)   // 55296
#define VLOFS (64 * RSV)            // 17408
#define FSMEM (FVH + 2 * 64 * RSV)  // 90112

template<bool MASKED>
__global__ __launch_bounds__(128, 2) void flash_attn(
    const bf16* __restrict__ Qh, const bf16* __restrict__ Ql,
    const bf16* __restrict__ Kh, const bf16* __restrict__ Kl,
    const bf16* __restrict__ Vh, const bf16* __restrict__ Vl,
    bf16* __restrict__ Oh, bf16* __restrict__ Ol)
{
    extern __shared__ char smem[];
    const uint32_t sb = smem_u32(smem);
    const int tid = threadIdx.x, lane = tid & 31, w = tid >> 5;   // w in 0..3
    const int qb = blockIdx.x;        // 0..7
    const int bh = blockIdx.y;
    const int qbase = qb * 64;
    const long qoff = (long)bh * C_ * 64 + (long)qbase * 64;
    const long koff = (long)bh * C_ * 64;
    const long voff = (long)bh * 64 * C_;

    auto loadQ = [&] {
        for (int i = tid; i < 64 * 8; i += 128) {
            int row = i >> 3, ch = i & 7;
            uint32_t off = (uint32_t)(row * RSQ + ch * 16);
            long go = qoff + (long)row * 64 + ch * 8;
            cpa16(sb + FQH + off, Qh + go);
            cpa16(sb + FQL + off, Ql + go);
        }
    };
    auto loadKV = [&](int j) {
        for (int i = tid; i < 128 * 8; i += 128) {
            int row = i >> 3, ch = i & 7;
            uint32_t off = (uint32_t)(row * RSQ + ch * 16);
            long go = koff + (long)(j * 128 + row) * 64 + ch * 8;
            cpa16(sb + FKH + off, Kh + go);
            cpa16(sb + FKH + KLOFS + off, Kl + go);
        }
        for (int i = tid; i < 64 * 16; i += 128) {
            int row = i >> 4, ch = i & 15;
            uint32_t off = (uint32_t)(row * RSV + ch * 16);
            long go = voff + (long)row * C_ + j * 128 + ch * 8;
            cpa16(sb + FVH + off, Vh + go);
            cpa16(sb + FVH + VLOFS + off, Vl + go);
        }
        asm volatile("cp.async.commit_group;" ::: "memory");
    };

    float oacc[8][4] = {};
    float sacc[16][4];
    float mA = -1e30f, mB = -1e30f, lA = 0.0f, lB = 0.0f;
    const int r0 = lane >> 2;
    const int c2 = (lane & 3) * 2;
    const int dA = qbase + w * 16 + r0;
    const int dB = dA + 8;

    loadQ();
    loadKV(0);

    for (int j = 0; j < 4; j++) {
        asm volatile("cp.async.wait_group 0;" ::: "memory");
        __syncthreads();

        // ---- S = Q K^T (split 3-combo) ----
#pragma unroll
        for (int nt = 0; nt < 16; nt++) {
            sacc[nt][0] = 0.f; sacc[nt][1] = 0.f; sacc[nt][2] = 0.f; sacc[nt][3] = 0.f;
        }
        const uint32_t qrow = (uint32_t)((w * 16 + (lane & 15)) * RSQ + ((lane >> 4) * 16));
        const uint32_t krow = (uint32_t)(((lane & 15)) * RSQ + ((lane >> 4) * 16));
#pragma unroll
        for (int kt = 0; kt < 4; kt++) {
            uint32_t ah[4], al[4];
            ldm_x4(ah, sb + FQH + qrow + kt * 32);
            ldm_x4(al, sb + FQL + qrow + kt * 32);
#pragma unroll
            for (int np = 0; np < 8; np++) {
                uint32_t bhh[4], bll[4];
                uint32_t baddr = sb + FKH + krow + (uint32_t)(np * 16 * RSQ + kt * 32);
                ldm_x4(bhh, baddr);
                ldm_x4(bll, baddr + KLOFS);
#pragma unroll
                for (int sel = 0; sel < 2; sel++) {
                    int nt = np * 2 + sel;
                    mma_bf16(sacc[nt], ah, bhh[sel], bhh[sel + 2]);
                    mma_bf16(sacc[nt], ah, bll[sel], bll[sel + 2]);
                    mma_bf16(sacc[nt], al, bhh[sel], bhh[sel + 2]);
                }
            }
        }

        // ---- scale + mask + online softmax ----
        float rmaxA = -1e30f, rmaxB = -1e30f;
#pragma unroll
        for (int nt = 0; nt < 16; nt++) {
            int cb = j * 128 + nt * 8 + c2;
#pragma unroll
            for (int q = 0; q < 2; q++) {
                float vA = sacc[nt][q] * 0.125f;
                float vB = sacc[nt][2 + q] * 0.125f;
                if (MASKED) {
                    if (cb + q <= dA) vA -= 12.5f;
                    if (cb + q <= dB) vB -= 12.5f;
                }
                sacc[nt][q] = vA; sacc[nt][2 + q] = vB;
                rmaxA = fmaxf(rmaxA, vA); rmaxB = fmaxf(rmaxB, vB);
            }
        }
        rmaxA = fmaxf(rmaxA, __shfl_xor_sync(0xffffffffu, rmaxA, 1));
        rmaxA = fmaxf(rmaxA, __shfl_xor_sync(0xffffffffu, rmaxA, 2));
        rmaxB = fmaxf(rmaxB, __shfl_xor_sync(0xffffffffu, rmaxB, 1));
        rmaxB = fmaxf(rmaxB, __shfl_xor_sync(0xffffffffu, rmaxB, 2));
        float nmA = fmaxf(mA, rmaxA), nmB = fmaxf(mB, rmaxB);
        float fA = __expf(mA - nmA), fB = __expf(mB - nmB);
        float sumA = 0.f, sumB = 0.f;
#pragma unroll
        for (int nt = 0; nt < 16; nt++) {
            float p0 = __expf(sacc[nt][0] - nmA);
            float p1 = __expf(sacc[nt][1] - nmA);
            float p2 = __expf(sacc[nt][2] - nmB);
            float p3 = __expf(sacc[nt][3] - nmB);
            sacc[nt][0] = p0; sacc[nt][1] = p1; sacc[nt][2] = p2; sacc[nt][3] = p3;
            sumA += p0 + p1; sumB += p2 + p3;
        }
        sumA += __shfl_xor_sync(0xffffffffu, sumA, 1);
        sumA += __shfl_xor_sync(0xffffffffu, sumA, 2);
        sumB += __shfl_xor_sync(0xffffffffu, sumB, 1);
        sumB += __shfl_xor_sync(0xffffffffu, sumB, 2);
        lA = lA * fA + sumA; lB = lB * fB + sumB;
        mA = nmA; mB = nmB;
#pragma unroll
        for (int nt = 0; nt < 8; nt++) {
            oacc[nt][0] *= fA; oacc[nt][1] *= fA;
            oacc[nt][2] *= fB; oacc[nt][3] *= fB;
        }

        // ---- O += P V ----
        const uint32_t vrow = (uint32_t)(((lane & 15)) * RSV + ((lane >> 4) * 16));
#pragma unroll
        for (int kt8 = 0; kt8 < 8; kt8++) {
            uint32_t ph[4], pl[4];
            {
                bf16 h0, l0, h1, l1;
                hilo(sacc[2 * kt8][0], h0, l0); hilo(sacc[2 * kt8][1], h1, l1);
                ph[0] = pack2(h0, h1); pl[0] = pack2(l0, l1);
                hilo(sacc[2 * kt8][2], h0, l0); hilo(sacc[2 * kt8][3], h1, l1);
                ph[1] = pack2(h0, h1); pl[1] = pack2(l0, l1);
                hilo(sacc[2 * kt8 + 1][0], h0, l0); hilo(sacc[2 * kt8 + 1][1], h1, l1);
                ph[2] = pack2(h0, h1); pl[2] = pack2(l0, l1);
                hilo(sacc[2 * kt8 + 1][2], h0, l0); hilo(sacc[2 * kt8 + 1][3], h1, l1);
                ph[3] = pack2(h0, h1); pl[3] = pack2(l0, l1);
            }
#pragma unroll
            for (int vp = 0; vp < 4; vp++) {
                uint32_t vhh[4], vll[4];
                uint32_t vaddr = sb + FVH + vrow + (uint32_t)(vp * 16 * RSV + kt8 * 32);
                ldm_x4(vhh, vaddr);
                ldm_x4(vll, vaddr + VLOFS);
#pragma unroll
                for (int sel = 0; sel < 2; sel++) {
                    int nt = vp * 2 + sel;
                    mma_bf16(oacc[nt], ph, vhh[sel], vhh[sel + 2]);
                    mma_bf16(oacc[nt], ph, vll[sel], vll[sel + 2]);
                    mma_bf16(oacc[nt], pl, vhh[sel], vhh[sel + 2]);
                }
            }
        }
        __syncthreads();
        if (j < 3) loadKV(j + 1);
    }

    const float invA = 1.0f / lA, invB = 1.0f / lB;
    const int b = bh >> 3, h = bh & 7;
    const long rowA = (long)(b * 512 + qbase + w * 16 + r0);
    const long rowB = rowA + 8;
#pragma unroll
    for (int nt = 0; nt < 8; nt++) {
        int col = h * 64 + nt * 8 + c2;
        float v0 = oacc[nt][0] * invA, v1 = oacc[nt][1] * invA;
        float v2 = oacc[nt][2] * invB, v3 = oacc[nt][3] * invB;
        bf16 h0, l0, h1, l1;
        hilo(v0, h0, l0); hilo(v1, h1, l1);
        *(bf162*)(Oh + rowA * 512 + col) = bf162{h0, h1};
        *(bf162*)(Ol + rowA * 512 + col) = bf162{l0, l1};
        hilo(v2, h0, l0); hilo(v3, h1, l1);
        *(bf162*)(Oh + rowB * 512 + col) = bf162{h0, h1};
        *(bf162*)(Ol + rowB * 512 + col) = bf162{l0, l1};
    }
}

// ---------------- reductions ----------------
__device__ __forceinline__ float warpRedSum(float v) {
#pragma unroll
    for (int o = 16; o > 0; o >>= 1) v += __shfl_xor_sync(0xffffffffu, v, o);
    return v;
}

// ---------------- conversions ----------------
__global__ void trans_hilo(const float* __restrict__ in, bf16* __restrict__ oh,
                           bf16* __restrict__ ol, int Rr, int Cc, long sDst1, long sDst2)
{
    __shared__ float t[32][33];
    int zz = blockIdx.z;
    long sbase = (long)zz * Rr * Cc;
    long dbase = (long)(zz >> 3) * sDst1 + (long)(zz & 7) * sDst2;
    int c0 = blockIdx.x * 32, r0 = blockIdx.y * 32;
    int tx = threadIdx.x, ty = threadIdx.y;
#pragma unroll
    for (int i = 0; i < 32; i += 8)
        t[ty + i][tx] = in[sbase + (long)(r0 + ty + i) * Cc + c0 + tx];
    __syncthreads();
#pragma unroll
    for (int i = 0; i < 32; i += 8) {
        float v = t[tx][ty + i];
        long o = dbase + (long)(c0 + ty + i) * Rr + (r0 + tx);
        bf16 h, l; hilo(v, h, l);
        oh[o] = h; ol[o] = l;
    }
}

__global__ __launch_bounds__(256) void flat_hilo(
    const float* __restrict__ in, bf16* __restrict__ oh, bf16* __restrict__ ol, int n)
{
    int i = blockIdx.x * 256 + threadIdx.x;
    if (i < n) { bf16 h, l; hilo(in[i], h, l); oh[i] = h; ol[i] = l; }
}

// ---------------- embedding + positional ----------------
__global__ __launch_bounds__(256) void embed_kernel(
    const float* __restrict__ embed, const int* __restrict__ dec,
    float* __restrict__ x, bf16* __restrict__ xh, bf16* __restrict__ xl)
{
    int idx = blockIdx.x * 256 + threadIdx.x;
    int r = idx / M_;
    int m = idx - r * M_;
    int c = r & (C_ - 1);
    int tok = dec[r];
    float denom = powf(10000.0f, (float)m / (float)(M_ - 1));
    float arg = (float)c / denom;
    float p = (m & 1) ? cosf(arg) : sinf(arg);
    float v = embed[(size_t)tok * M_ + m] + p;
    x[idx] = v;
    bf16 h, l; hilo(v, h, l);
    xh[idx] = h; xl[idx] = l;
}

// ---------------- x = LN(x + y)*g + b ; warp-per-row ----------------
__global__ __launch_bounds__(128) void add_ln_kernel(
    float* __restrict__ x, const float* __restrict__ y,
    const float* __restrict__ g, const float* __restrict__ b,
    bf16* __restrict__ xh, bf16* __restrict__ xl)
{
    const int wid = threadIdx.x >> 5, lane = threadIdx.x & 31;
    const long row = (long)blockIdx.x * 4 + wid;
    float* xr = x + row * M_;
    const float* yr = y + row * M_;
    float v[16];
#pragma unroll
    for (int i = 0; i < 4; i++) {
        float4 a = ((float4*)xr)[lane + 32 * i];
        float4 c = ((const float4*)yr)[lane + 32 * i];
        v[4 * i + 0] = a.x + c.x; v[4 * i + 1] = a.y + c.y;
        v[4 * i + 2] = a.z + c.z; v[4 * i + 3] = a.w + c.w;
    }
    float s = 0.0f;
#pragma unroll
    for (int j = 0; j < 16; j++) s += v[j];
    s = warpRedSum(s);
    const float mu = s * (1.0f / M_);
    float q = 0.0f;
#pragma unroll
    for (int j = 0; j < 16; j++) { float d = v[j] - mu; q += d * d; }
    q = warpRedSum(q);
    const float inv = rsqrtf(q * (1.0f / M_) + 1e-5f);
#pragma unroll
    for (int i = 0; i < 4; i++) {
        float4 gg = ((const float4*)g)[lane + 32 * i];
        float4 bb = ((const float4*)b)[lane + 32 * i];
        float o0 = (v[4 * i + 0] - mu) * inv * gg.x + bb.x;
        float o1 = (v[4 * i + 1] - mu) * inv * gg.y + bb.y;
        float o2 = (v[4 * i + 2] - mu) * inv * gg.z + bb.z;
        float o3 = (v[4 * i + 3] - mu) * inv * gg.w + bb.w;
        float4 of = {o0, o1, o2, o3};
        ((float4*)xr)[lane + 32 * i] = of;
        long base = row * M_ + (lane + 32 * i) * 4;
        bf16 h0, l0, h1, l1, h2, l2, h3, l3;
        hilo(o0, h0, l0); hilo(o1, h1, l1);
        hilo(o2, h2, l2); hilo(o3, h3, l3);
        bf162 H0{h0, h1}, H1{h2, h3}, L0{l0, l1}, L1{l2, l3};
        *(bf162*)(xh + base) = H0; *(bf162*)(xh + base + 2) = H1;
        *(bf162*)(xl + base) = L0; *(bf162*)(xl + base + 2) = L1;
    }
}

// ---------------- final softmax: float4-vectorized online pass + normalize ----------------
__global__ __launch_bounds__(512) void softmax_final_kernel(float* __restrict__ out)
{
    long row = blockIdx.x;
    float4* p4 = (float4*)(out + row * (long)T_);
    const int N4 = T_ / 4;
    int t = threadIdx.x;
    float m = -1e30f, s = 0.0f;
    for (int i = t; i < N4; i += 512) {
        float4 q = p4[i];
        float vv[4] = {q.x, q.y, q.z, q.w};
#pragma unroll
        for (int j = 0; j < 4; j++) {
            float v = vv[j];
            if (v > m) { s = s * __expf(m - v) + 1.0f; m = v; }
            else s += __expf(v - m);
        }
    }
#pragma unroll
    for (int o = 16; o > 0; o >>= 1) {
        float m2 = __shfl_xor_sync(0xffffffffu, m, o);
        float s2 = __shfl_xor_sync(0xffffffffu, s, o);
        float M = fmaxf(m, m2);
        s = s * __expf(m - M) + s2 * __expf(m2 - M);
        m = M;
    }
    __shared__ float rm[16], rs[16];
    int wid = t >> 5, lane = t & 31;
    if (!lane) { rm[wid] = m; rs[wid] = s; }
    __syncthreads();
    float M = rm[0], S = rs[0];
#pragma unroll
    for (int j = 1; j < 16; j++) {
        float M2 = fmaxf(M, rm[j]);
        S = S * __expf(M - M2) + rs[j] * __expf(rm[j] - M2);
        M = M2;
    }
    float inv = 1.0f / S;
    for (int i = t; i < N4; i += 512) {
        float4 q = p4[i];
        q.x = __expf(q.x - M) * inv;
        q.y = __expf(q.y - M) * inv;
        q.z = __expf(q.z - M) * inv;
        q.w = __expf(q.w - M) * inv;
        p4[i] = q;
    }
}

// ---------------- driver ----------------
#define SMEM64  (3 * (2 * 128 * 80 + 2 * 64 * 80))    // 92160

extern "C" void kernel_launch(void* const* d_in, const int* in_sizes, int n_in,
                              void* d_out, int out_size)
{
    const float* enc = (const float*)d_in[0];
    const int*   dec = (const int*)d_in[1];
    const float* emb = (const float*)d_in[2];
    const float* wq  = (const float*)d_in[3];
    const float* wk  = (const float*)d_in[4];
    const float* wv  = (const float*)d_in[5];
    const float* wo  = (const float*)d_in[6];
    const float* w1  = (const float*)d_in[7];
    const float* b1  = (const float*)d_in[8];
    const float* w2  = (const float*)d_in[9];
    const float* b2  = (const float*)d_in[10];
    const float* lng = (const float*)d_in[11];
    const float* lnb = (const float*)d_in[12];
    const float* wf  = (const float*)d_in[13];
    const float* bf  = (const float*)d_in[14];
    float* out = (float*)d_out;

    float *px, *ptmp;
    bf16 *pxh, *pxl, *pech, *pecl, *pqh, *pql, *pkh, *pkl, *pvth, *pvtl;
    bf16 *pckh, *pckl, *pcvth, *pcvtl;
    bf16 *pph, *ppl, *pfh, *pfl;
    bf16 *wqkvh, *wqkvl, *woh, *wol, *w1h, *w1l, *w2h, *w2l, *wfh, *wfl;
    cudaGetSymbolAddress((void**)&px, g_x);
    cudaGetSymbolAddress((void**)&ptmp, g_tmp);
    cudaGetSymbolAddress((void**)&pxh, g_xh);   cudaGetSymbolAddress((void**)&pxl, g_xl);
    cudaGetSymbolAddress((void**)&pech, g_ench);cudaGetSymbolAddress((void**)&pecl, g_encl);
    cudaGetSymbolAddress((void**)&pqh, g_qh);   cudaGetSymbolAddress((void**)&pql, g_ql);
    cudaGetSymbolAddress((void**)&pkh, g_kh);   cudaGetSymbolAddress((void**)&pkl, g_kl);
    cudaGetSymbolAddress((void**)&pvth, g_vth); cudaGetSymbolAddress((void**)&pvtl, g_vtl);
    cudaGetSymbolAddress((void**)&pckh, g_ckh); cudaGetSymbolAddress((void**)&pckl, g_ckl);
    cudaGetSymbolAddress((void**)&pcvth, g_cvth); cudaGetSymbolAddress((void**)&pcvtl, g_cvtl);
    cudaGetSymbolAddress((void**)&pph, g_preh); cudaGetSymbolAddress((void**)&ppl, g_prel);
    cudaGetSymbolAddress((void**)&pfh, g_ffh);  cudaGetSymbolAddress((void**)&pfl, g_ffl);
    cudaGetSymbolAddress((void**)&wqkvh, g_wqkv_h); cudaGetSymbolAddress((void**)&wqkvl, g_wqkv_l);
    cudaGetSymbolAddress((void**)&woh, g_wot_h);cudaGetSymbolAddress((void**)&wol, g_wot_l);
    cudaGetSymbolAddress((void**)&w1h, g_w1t_h);cudaGetSymbolAddress((void**)&w1l, g_w1t_l);
    cudaGetSymbolAddress((void**)&w2h, g_w2t_h);cudaGetSymbolAddress((void**)&w2l, g_w2t_l);
    cudaGetSymbolAddress((void**)&wfh, g_wft_h);cudaGetSymbolAddress((void**)&wfl, g_wft_l);

    cudaFuncSetAttribute(tcmm<64,3,2,1,4,false,false>,  cudaFuncAttributeMaxDynamicSharedMemorySize, SMEM64);
    cudaFuncSetAttribute(tcmm<64,3,2,1,5,false,false>,  cudaFuncAttributeMaxDynamicSharedMemorySize, SMEM64);
    cudaFuncSetAttribute(tcmm<64,3,2,1,2,false,false>,  cudaFuncAttributeMaxDynamicSharedMemorySize, SMEM64);
    cudaFuncSetAttribute(tcmm<64,3,2,0,0,false,false>,  cudaFuncAttributeMaxDynamicSharedMemorySize, SMEM64);
    cudaFuncSetAttribute(tcmm<64,3,2,1,0,true,true>,    cudaFuncAttributeMaxDynamicSharedMemorySize, SMEM64);
    cudaFuncSetAttribute(tcmm<64,3,2,0,0,true,false>,   cudaFuncAttributeMaxDynamicSharedMemorySize, SMEM64);
    cudaFuncSetAttribute(flash_attn<true>,  cudaFuncAttributeMaxDynamicSharedMemorySize, FSMEM);
    cudaFuncSetAttribute(flash_attn<false>, cudaFuncAttributeMaxDynamicSharedMemorySize, FSMEM);

    const long MM = (long)M_ * M_;
    dim3 blk(32, 8);
    trans_hilo<<<dim3(2, 16, 96), blk>>>(wq, wqkvh,          wqkvl,          512, 64, 3 * MM, 64 * 512);
    trans_hilo<<<dim3(2, 16, 96), blk>>>(wk, wqkvh + MM,     wqkvl + MM,     512, 64, 3 * MM, 64 * 512);
    trans_hilo<<<dim3(2, 16, 96), blk>>>(wv, wqkvh + 2 * MM, wqkvl + 2 * MM, 512, 64, 3 * MM, 64 * 512);
    trans_hilo<<<dim3(16, 16, 12), blk>>>(wo, woh, wol, 512, 512,  8 * MM, MM);
    trans_hilo<<<dim3(64, 16, 6), blk>>>(w1, w1h, w1l, 512, 2048, 8L * 512 * 2048, (long)512 * 2048);
    trans_hilo<<<dim3(16, 64, 6), blk>>>(w2, w2h, w2l, 2048, 512, 8L * 512 * 2048, (long)512 * 2048);
    flat_hilo<<<(T_ * M_) / 256, 256>>>(wf, wfh, wfl, T_ * M_);
    flat_hilo<<<RM / 256, 256>>>(enc, pech, pecl, RM);

    embed_kernel<<<RM / 256, 256>>>(emb, dec, px, pxh, pxl);

    // all 6 layers' cross-attention K|V upfront (block (2l+1), k-section)
    tcmm<64,3,2,1,5,false,false><<<dim3(16, 16, 6), 256, SMEM64>>>(
        pech, pecl, 512, 0, wqkvh + 3 * MM + MM, wqkvl + 3 * MM + MM, 512, 6 * MM, nullptr,
        nullptr, pckh, pckl, pcvth, pcvtl, 0, 0, 512, 512, 0);

    for (int l = 0; l < L_; l++) {
        for (int s = 0; s < 2; s++) {
            long wOff = (long)(l * 2 + s) * 3 * MM;
            long woOff = (long)(l * 2 + s) * MM;

            if (s == 0) {
                tcmm<64,3,2,1,4,false,false><<<dim3(24, 16, 1), 256, SMEM64>>>(
                    pxh, pxl, 512, 0, wqkvh + wOff, wqkvl + wOff, 512, 0, nullptr,
                    nullptr, nullptr, nullptr, nullptr, nullptr, 0, 0, 512, 0, 0);
                flash_attn<true><<<dim3(8, 32), 128, FSMEM>>>(
                    pqh, pql, pkh, pkl, pvth, pvtl, pph, ppl);
            } else {
                tcmm<64,3,2,1,2,false,false><<<dim3(8, 16, 1), 256, SMEM64>>>(
                    pxh, pxl, 512, 0, wqkvh + wOff, wqkvl + wOff, 512, 0, nullptr,
                    nullptr, pqh, pql, nullptr, nullptr, 0, 0, 512, 0, 0);
                flash_attn<false><<<dim3(8, 32), 128, FSMEM>>>(
                    pqh, pql, pckh + (long)l * RM, pckl + (long)l * RM,
                    pcvth + (long)l * RM, pcvtl + (long)l * RM, pph, ppl);
            }

            tcmm<64,3,2,0,0,false,false><<<dim3(8, 16, 1), 256, SMEM64>>>(
                pph, ppl, 512, 0, woh + woOff, wol + woOff, 512, 0, nullptr,
                ptmp, nullptr, nullptr, nullptr, nullptr, 512, 0, 512, 0, 0);

            add_ln_kernel<<<R_ / 4, 128>>>(px, ptmp,
                lng + (size_t)(l * 3 + s) * M_, lnb + (size_t)(l * 3 + s) * M_, pxh, pxl);
        }
        long w1Off = (long)l * M_ * F_;
        tcmm<64,3,2,1,0,true,true><<<dim3(32, 16, 1), 256, SMEM64>>>(
            pxh, pxl, 512, 0, w1h + w1Off, w1l + w1Off, 512, 0, b1 + (size_t)l * F_,
            nullptr, pfh, pfl, nullptr, nullptr, 2048, 0, 512, 0, 0);
        tcmm<64,3,2,0,0,true,false><<<dim3(8, 16, 1), 256, SMEM64>>>(
            pfh, pfl, 2048, 0, w2h + w1Off, w2l + w1Off, 2048, 0, b2 + (size_t)l * M_,
            ptmp, nullptr, nullptr, nullptr, nullptr, 512, 0, 2048, 0, 0);
        add_ln_kernel<<<R_ / 4, 128>>>(px, ptmp,
            lng + (size_t)(l * 3 + 2) * M_, lnb + (size_t)(l * 3 + 2) * M_, pxh, pxl);
    }

    // vocab projection: BN=64, 2 CTA/SM, swapped grid (weight-tile sharers adjacent)
    tcmm<64,3,2,0,0,true,false><<<dim3(16, 500, 1), 256, SMEM64>>>(
        pxh, pxl, 512, 0, wfh, wfl, 512, 0, bf,
        out, nullptr, nullptr, nullptr, nullptr, 32000, 0, 512, 0, 1);
    softmax_final_kernel<<<R_, 512>>>(out);
}

// round 15
// speedup vs baseline: 1.0172x; 1.0172x over previous
#include <cuda_runtime.h>
#include <cuda_bf16.h>
#include <cstdint>

typedef __nv_bfloat16 bf16;
typedef __nv_bfloat162 bf162;

#define B_ 4
#define C_ 512
#define M_ 512
#define H_ 8
#define F_ 2048
#define L_ 6
#define T_ 32000
#define R_ 2048
#define RM (R_ * M_)

// ---------------- scratch ----------------
__device__ float g_x[RM];
__device__ bf16  g_xh[RM],  g_xl[RM];
__device__ bf16  g_ench[RM], g_encl[RM];
__device__ bf16  g_qh[RM],  g_ql[RM];
__device__ bf16  g_kh[RM],  g_kl[RM];
__device__ bf16  g_vth[RM], g_vtl[RM];             // (b,h,v,c)
__device__ bf16  g_ckh[L_*RM], g_ckl[L_*RM];       // per-layer cross K
__device__ bf16  g_cvth[L_*RM], g_cvtl[L_*RM];     // per-layer cross vT
__device__ bf16  g_preh[RM], g_prel[RM];
__device__ bf16  g_ffh[R_ * F_],  g_ffl[R_ * F_];
__device__ float g_tmp[RM];
__device__ bf16 g_wqkv_h[L_*2*3*M_*M_], g_wqkv_l[L_*2*3*M_*M_];
__device__ bf16 g_wot_h[L_*2*M_*M_], g_wot_l[L_*2*M_*M_];
__device__ bf16 g_w1t_h[L_*F_*M_],   g_w1t_l[L_*F_*M_];
__device__ bf16 g_w2t_h[L_*M_*F_],   g_w2t_l[L_*M_*F_];
__device__ bf16 g_wft_h[(size_t)T_*M_], g_wft_l[(size_t)T_*M_];

// ---------------- helpers ----------------
__device__ __forceinline__ uint32_t smem_u32(const void* p) {
    uint32_t a;
    asm("{ .reg .u64 t; cvta.to.shared.u64 t, %1; cvt.u32.u64 %0, t; }" : "=r"(a) : "l"(p));
    return a;
}
__device__ __forceinline__ void cpa16(uint32_t dst, const void* src) {
    asm volatile("cp.async.cg.shared.global [%0], [%1], 16;" :: "r"(dst), "l"(src));
}
__device__ __forceinline__ void ldm_x4(uint32_t* r, uint32_t addr) {
    asm volatile("ldmatrix.sync.aligned.m8n8.x4.shared.b16 {%0,%1,%2,%3}, [%4];"
                 : "=r"(r[0]), "=r"(r[1]), "=r"(r[2]), "=r"(r[3]) : "r"(addr));
}
__device__ __forceinline__ void mma_bf16(float* c, const uint32_t* a, uint32_t b0, uint32_t b1) {
    asm volatile("mma.sync.aligned.m16n8k16.row.col.f32.bf16.bf16.f32 "
                 "{%0,%1,%2,%3}, {%4,%5,%6,%7}, {%8,%9}, {%0,%1,%2,%3};"
                 : "+f"(c[0]), "+f"(c[1]), "+f"(c[2]), "+f"(c[3])
                 : "r"(a[0]), "r"(a[1]), "r"(a[2]), "r"(a[3]), "r"(b0), "r"(b1));
}
__device__ __forceinline__ void hilo(float v, bf16& h, bf16& l) {
    h = __float2bfloat16(v);
    l = __float2bfloat16(v - __bfloat162float(h));
}
__device__ __forceinline__ uint32_t pack2(bf16 a, bf16 b) {
    bf162 t{a, b};
    return *reinterpret_cast<uint32_t*>(&t);
}

// ---------------- split-bf16 tensor-core GEMM (mma.sync, NS-deep pipeline) ----------------
// EPI: 0 fp32 row-major; 1 hi/lo bf16 (layout per CB)
// CB:  0 plain  2 qkv-scatter  4 fused-qkv scatter  5 cross-KV scatter
template<int BN, int NS, int MINB, int EPI, int CB, bool BIAS, bool RELU>
__global__ __launch_bounds__(256, MINB) void tcmm(
    const bf16* __restrict__ Ah, const bf16* __restrict__ Al, int lda, long sA,
    const bf16* __restrict__ Bh, const bf16* __restrict__ Bl, int ldb, long sB,
    const float* __restrict__ bias,
    float* __restrict__ Cf, bf16* __restrict__ Ch, bf16* __restrict__ Cl,
    bf16* __restrict__ Dh, bf16* __restrict__ Dl,
    int ldc, long sC, int Kd, int nOfs, int swp)
{
    constexpr int WX = (BN == 128) ? 4 : 2;
    constexpr int WY = 8 / WX;
    constexpr int WM = 128 / WY;
    constexpr int WN = BN / WX;
    constexpr int MT = WM / 16;
    constexpr int NT = WN / 8;
    constexpr int RS = 80;
    constexpr int AS = 128 * RS;
    constexpr int BS = BN * RS;
    constexpr int STAGE = 2 * AS + 2 * BS;

    extern __shared__ char smem[];
    const uint32_t sb = smem_u32(smem);
    const int tid = threadIdx.x;
    const int z = blockIdx.z;
    int m0, n0;
    if (swp) { m0 = blockIdx.x * 128; n0 = blockIdx.y * BN; }
    else     { m0 = blockIdx.y * 128; n0 = blockIdx.x * BN; }
    const int lane = tid & 31, w = tid >> 5;
    const int wy = w % WY, wx = w / WY;

    const bf16* Abh = Ah + (long)z * sA;
    const bf16* Abl = Al + (long)z * sA;
    const bf16* Bbh = Bh + (long)z * sB;
    const bf16* Bbl = Bl + (long)z * sB;

    const int S = Kd >> 5;
    float acc[MT][NT][4] = {};

    auto loadStage = [&](int s) {
        const uint32_t buf = sb + (uint32_t)((NS == 4) ? (s & 3) : (s % 3)) * STAGE;
        const long k0 = (long)s << 5;
        for (int i = tid; i < 128 * 4; i += 256) {
            int row = i >> 2, ch = i & 3;
            uint32_t off = (uint32_t)(row * RS + ch * 16);
            long go = (long)(m0 + row) * lda + k0 + ch * 8;
            cpa16(buf + off, Abh + go);
            cpa16(buf + AS + off, Abl + go);
        }
        for (int i = tid; i < BN * 4; i += 256) {
            int row = i >> 2, ch = i & 3;
            uint32_t off = (uint32_t)(row * RS + ch * 16);
            long go = (long)(n0 + row) * ldb + k0 + ch * 8;
            cpa16(buf + 2 * AS + off, Bbh + go);
            cpa16(buf + 2 * AS + BS + off, Bbl + go);
        }
        asm volatile("cp.async.commit_group;" ::: "memory");
    };

    loadStage(0);
    if (S > 1) loadStage(1);
    if (NS == 4 && S > 2) loadStage(2);
    for (int s = 0; s < S; s++) {
        const int rem = S - 1 - s;
        if (NS == 4) {
            if (rem >= 2)      asm volatile("cp.async.wait_group 2;" ::: "memory");
            else if (rem == 1) asm volatile("cp.async.wait_group 1;" ::: "memory");
            else               asm volatile("cp.async.wait_group 0;" ::: "memory");
        } else {
            if (rem >= 1)      asm volatile("cp.async.wait_group 1;" ::: "memory");
            else               asm volatile("cp.async.wait_group 0;" ::: "memory");
        }
        __syncthreads();
        if (s + NS - 1 < S) loadStage(s + NS - 1);
        const uint32_t buf = sb + (uint32_t)((NS == 4) ? (s & 3) : (s % 3)) * STAGE;
        const uint32_t aRowOff = (uint32_t)((wy * WM + (lane & 15)) * RS);
        const uint32_t bRowOff = (uint32_t)((wx * WN + (lane & 15)) * RS);
#pragma unroll
        for (int kk = 0; kk < 2; kk++) {
            const uint32_t kOff = (uint32_t)(kk * 32 + ((lane >> 4) * 16));
            uint32_t ah[MT][4], al[MT][4], bh[2][4], bl[2][4];
#pragma unroll
            for (int mt = 0; mt < MT; mt++) {
                uint32_t ad = buf + aRowOff + (uint32_t)(mt * 16 * RS) + kOff;
                ldm_x4(ah[mt], ad);
                ldm_x4(al[mt], ad + AS);
            }
#pragma unroll
            for (int np = 0; np < 2; np++) {
                uint32_t bd = buf + 2 * AS + bRowOff + (uint32_t)(np * 16 * RS) + kOff;
                ldm_x4(bh[np], bd);
                ldm_x4(bl[np], bd + BS);
            }
#pragma unroll
            for (int mt = 0; mt < MT; mt++) {
#pragma unroll
                for (int nt = 0; nt < NT; nt++) {
                    const int np = nt >> 1, sel = nt & 1;
                    mma_bf16(acc[mt][nt], ah[mt], bh[np][sel], bh[np][sel + 2]);
                    mma_bf16(acc[mt][nt], ah[mt], bl[np][sel], bl[np][sel + 2]);
                    mma_bf16(acc[mt][nt], al[mt], bh[np][sel], bh[np][sel + 2]);
                }
            }
        }
    }

    // epilogue
    const int rBase = m0 + wy * WM + (lane >> 2);
    const int cBase = n0 + wx * WN + (lane & 3) * 2;
#pragma unroll
    for (int mt = 0; mt < MT; mt++) {
#pragma unroll
        for (int nt = 0; nt < NT; nt++) {
#pragma unroll
            for (int half = 0; half < 2; half++) {
                const int r = rBase + mt * 16 + half * 8;
                const int c = cBase + nt * 8;
                float v0 = acc[mt][nt][half * 2];
                float v1 = acc[mt][nt][half * 2 + 1];
                if (BIAS) { v0 += bias[c]; v1 += bias[c + 1]; }
                if (RELU) { v0 = fmaxf(v0, 0.0f); v1 = fmaxf(v1, 0.0f); }
                if (EPI == 0) {
                    long idx = (long)z * sC + (long)r * ldc + c;
                    float2 o = {v0, v1};
                    *(float2*)(Cf + idx) = o;
                } else if (CB == 4) {
                    const int nn = c + nOfs;
                    bf16 h0, l0, h1, l1;
                    hilo(v0, h0, l0); hilo(v1, h1, l1);
                    if (nn < 1024) {
                        int kc = nn & 511;
                        long idx = ((long)(r >> 9) * 8 + (kc >> 6)) * 32768 + (long)(r & 511) * 64 + (kc & 63);
                        bf162 Hh{h0, h1}, Ll{l0, l1};
                        if (nn < 512) { *(bf162*)(g_qh + idx) = Hh; *(bf162*)(g_ql + idx) = Ll; }
                        else          { *(bf162*)(g_kh + idx) = Hh; *(bf162*)(g_kl + idx) = Ll; }
                    } else {
                        int vc = nn - 1024;
                        long i0 = ((long)(r >> 9) * 512 + vc) * 512 + (r & 511);
                        g_vth[i0] = h0; g_vtl[i0] = l0;
                        g_vth[i0 + 512] = h1; g_vtl[i0 + 512] = l1;
                    }
                } else if (CB == 5) {
                    const int nn = c + nOfs;
                    const long lofs = (long)z * RM;
                    bf16 h0, l0, h1, l1;
                    hilo(v0, h0, l0); hilo(v1, h1, l1);
                    if (nn < 1024) {
                        int kc = nn & 511;
                        long idx = lofs + ((long)(r >> 9) * 8 + (kc >> 6)) * 32768 + (long)(r & 511) * 64 + (kc & 63);
                        bf162 Hh{h0, h1}, Ll{l0, l1};
                        *(bf162*)(Ch + idx) = Hh; *(bf162*)(Cl + idx) = Ll;
                    } else {
                        int vc = nn - 1024;
                        long i0 = lofs + ((long)(r >> 9) * 512 + vc) * 512 + (r & 511);
                        Dh[i0] = h0; Dl[i0] = l0;
                        Dh[i0 + 512] = h1; Dl[i0 + 512] = l1;
                    }
                } else {
                    long idx;
                    if (CB == 0) idx = (long)z * sC + (long)r * ldc + c;
                    else         idx = (((long)(r >> 9) * 8 + (c >> 6)) << 15) + (long)(r & 511) * 64 + (c & 63);
                    bf16 h0, l0, h1, l1;
                    hilo(v0, h0, l0); hilo(v1, h1, l1);
                    bf162 Hh{h0, h1}, Ll{l0, l1};
                    *(bf162*)(Ch + idx) = Hh;
                    *(bf162*)(Cl + idx) = Ll;
                }
            }
        }
    }
}

// ---------------- fused flash attention (128-row Q tiles, double-buffered KV) ----------------
#define RSQ 144
#define RSV 272
#define FQH 0
#define FQL (128 * RSQ)
#define FK0 (2 * 128 * RSQ)
#define FKSZ (128 * RSQ)
#define FV0 (FK0 + 4 * FKSZ)
#define FVSZ (64 * RSV)
#define FSMEM (FV0 + 4 * FVSZ)   // 180224

template<bool MASKED>
__global__ __launch_bounds__(256) void flash_attn(
    const bf16* __restrict__ Qh, const bf16* __restrict__ Ql,
    const bf16* __restrict__ Kh, const bf16* __restrict__ Kl,
    const bf16* __restrict__ Vh, const bf16* __restrict__ Vl,
    bf16* __restrict__ Oh, bf16* __restrict__ Ol)
{
    extern __shared__ char smem[];
    const uint32_t sb = smem_u32(smem);
    const int tid = threadIdx.x, lane = tid & 31, w = tid >> 5;
    const int qb = blockIdx.x;
    const int bh = blockIdx.y;
    const int qbase = qb * 128;
    const long qoff = (long)bh * C_ * 64 + (long)qbase * 64;
    const long koff = (long)bh * C_ * 64;
    const long voff = (long)bh * 64 * C_;

    auto loadQ = [&] {
        for (int i = tid; i < 128 * 8; i += 256) {
            int row = i >> 3, ch = i & 7;
            uint32_t off = (uint32_t)(row * RSQ + ch * 16);
            long go = qoff + (long)row * 64 + ch * 8;
            cpa16(sb + FQH + off, Qh + go);
            cpa16(sb + FQL + off, Ql + go);
        }
    };
    auto loadKV = [&](int j) {
        uint32_t kb = FK0 + (uint32_t)(j & 1) * 2 * FKSZ;
        for (int i = tid; i < 128 * 8; i += 256) {
            int row = i >> 3, ch = i & 7;
            uint32_t off = (uint32_t)(row * RSQ + ch * 16);
            long go = koff + (long)(j * 128 + row) * 64 + ch * 8;
            cpa16(sb + kb + off, Kh + go);
            cpa16(sb + kb + FKSZ + off, Kl + go);
        }
        uint32_t vb = FV0 + (uint32_t)(j & 1) * 2 * FVSZ;
        for (int i = tid; i < 64 * 16; i += 256) {
            int row = i >> 4, ch = i & 15;
            uint32_t off = (uint32_t)(row * RSV + ch * 16);
            long go = voff + (long)row * C_ + j * 128 + ch * 8;
            cpa16(sb + vb + off, Vh + go);
            cpa16(sb + vb + FVSZ + off, Vl + go);
        }
        asm volatile("cp.async.commit_group;" ::: "memory");
    };

    float oacc[8][4] = {};
    float sacc[16][4];
    float mA = -1e30f, mB = -1e30f, lA = 0.0f, lB = 0.0f;
    const int r0 = lane >> 2;
    const int c2 = (lane & 3) * 2;
    const int dA = qbase + w * 16 + r0;
    const int dB = dA + 8;

    loadQ();
    loadKV(0);
    loadKV(1);

    for (int j = 0; j < 4; j++) {
        if (j < 3) asm volatile("cp.async.wait_group 1;" ::: "memory");
        else       asm volatile("cp.async.wait_group 0;" ::: "memory");
        __syncthreads();
        const uint32_t kb = FK0 + (uint32_t)(j & 1) * 2 * FKSZ;
        const uint32_t vb = FV0 + (uint32_t)(j & 1) * 2 * FVSZ;

#pragma unroll
        for (int nt = 0; nt < 16; nt++) {
            sacc[nt][0] = 0.f; sacc[nt][1] = 0.f; sacc[nt][2] = 0.f; sacc[nt][3] = 0.f;
        }
        const uint32_t qrow = (uint32_t)((w * 16 + (lane & 15)) * RSQ + ((lane >> 4) * 16));
        const uint32_t krow = (uint32_t)(((lane & 15)) * RSQ + ((lane >> 4) * 16));
#pragma unroll
        for (int kt = 0; kt < 4; kt++) {
            uint32_t ah[4], al[4];
            ldm_x4(ah, sb + FQH + qrow + kt * 32);
            ldm_x4(al, sb + FQL + qrow + kt * 32);
#pragma unroll
            for (int np = 0; np < 8; np++) {
                uint32_t bhh[4], bll[4];
                uint32_t baddr = sb + kb + krow + (uint32_t)(np * 16 * RSQ + kt * 32);
                ldm_x4(bhh, baddr);
                ldm_x4(bll, baddr + FKSZ);
#pragma unroll
                for (int sel = 0; sel < 2; sel++) {
                    int nt = np * 2 + sel;
                    mma_bf16(sacc[nt], ah, bhh[sel], bhh[sel + 2]);
                    mma_bf16(sacc[nt], ah, bll[sel], bll[sel + 2]);
                    mma_bf16(sacc[nt], al, bhh[sel], bhh[sel + 2]);
                }
            }
        }

        float rmaxA = -1e30f, rmaxB = -1e30f;
#pragma unroll
        for (int nt = 0; nt < 16; nt++) {
            int cb = j * 128 + nt * 8 + c2;
#pragma unroll
            for (int q = 0; q < 2; q++) {
                float vA = sacc[nt][q] * 0.125f;
                float vB = sacc[nt][2 + q] * 0.125f;
                if (MASKED) {
                    if (cb + q <= dA) vA -= 12.5f;
                    if (cb + q <= dB) vB -= 12.5f;
                }
                sacc[nt][q] = vA; sacc[nt][2 + q] = vB;
                rmaxA = fmaxf(rmaxA, vA); rmaxB = fmaxf(rmaxB, vB);
            }
        }
        rmaxA = fmaxf(rmaxA, __shfl_xor_sync(0xffffffffu, rmaxA, 1));
        rmaxA = fmaxf(rmaxA, __shfl_xor_sync(0xffffffffu, rmaxA, 2));
        rmaxB = fmaxf(rmaxB, __shfl_xor_sync(0xffffffffu, rmaxB, 1));
        rmaxB = fmaxf(rmaxB, __shfl_xor_sync(0xffffffffu, rmaxB, 2));
        float nmA = fmaxf(mA, rmaxA), nmB = fmaxf(mB, rmaxB);
        float fA = __expf(mA - nmA), fB = __expf(mB - nmB);
        float sumA = 0.f, sumB = 0.f;
#pragma unroll
        for (int nt = 0; nt < 16; nt++) {
            float p0 = __expf(sacc[nt][0] - nmA);
            float p1 = __expf(sacc[nt][1] - nmA);
            float p2 = __expf(sacc[nt][2] - nmB);
            float p3 = __expf(sacc[nt][3] - nmB);
            sacc[nt][0] = p0; sacc[nt][1] = p1; sacc[nt][2] = p2; sacc[nt][3] = p3;
            sumA += p0 + p1; sumB += p2 + p3;
        }
        sumA += __shfl_xor_sync(0xffffffffu, sumA, 1);
        sumA += __shfl_xor_sync(0xffffffffu, sumA, 2);
        sumB += __shfl_xor_sync(0xffffffffu, sumB, 1);
        sumB += __shfl_xor_sync(0xffffffffu, sumB, 2);
        lA = lA * fA + sumA; lB = lB * fB + sumB;
        mA = nmA; mB = nmB;
#pragma unroll
        for (int nt = 0; nt < 8; nt++) {
            oacc[nt][0] *= fA; oacc[nt][1] *= fA;
            oacc[nt][2] *= fB; oacc[nt][3] *= fB;
        }

        const uint32_t vrow = (uint32_t)(((lane & 15)) * RSV + ((lane >> 4) * 16));
#pragma unroll
        for (int kt8 = 0; kt8 < 8; kt8++) {
            uint32_t ph[4], pl[4];
            {
                bf16 h0, l0, h1, l1;
                hilo(sacc[2 * kt8][0], h0, l0); hilo(sacc[2 * kt8][1], h1, l1);
                ph[0] = pack2(h0, h1); pl[0] = pack2(l0, l1);
                hilo(sacc[2 * kt8][2], h0, l0); hilo(sacc[2 * kt8][3], h1, l1);
                ph[1] = pack2(h0, h1); pl[1] = pack2(l0, l1);
                hilo(sacc[2 * kt8 + 1][0], h0, l0); hilo(sacc[2 * kt8 + 1][1], h1, l1);
                ph[2] = pack2(h0, h1); pl[2] = pack2(l0, l1);
                hilo(sacc[2 * kt8 + 1][2], h0, l0); hilo(sacc[2 * kt8 + 1][3], h1, l1);
                ph[3] = pack2(h0, h1); pl[3] = pack2(l0, l1);
            }
#pragma unroll
            for (int vp = 0; vp < 4; vp++) {
                uint32_t vhh[4], vll[4];
                uint32_t vaddr = sb + vb + vrow + (uint32_t)(vp * 16 * RSV + kt8 * 32);
                ldm_x4(vhh, vaddr);
                ldm_x4(vll, vaddr + FVSZ);
#pragma unroll
                for (int sel = 0; sel < 2; sel++) {
                    int nt = vp * 2 + sel;
                    mma_bf16(oacc[nt], ph, vhh[sel], vhh[sel + 2]);
                    mma_bf16(oacc[nt], ph, vll[sel], vll[sel + 2]);
                    mma_bf16(oacc[nt], pl, vhh[sel], vhh[sel + 2]);
                }
            }
        }
        __syncthreads();
        if (j + 2 < 4) loadKV(j + 2);
    }

    const float invA = 1.0f / lA, invB = 1.0f / lB;
    const int b = bh >> 3, h = bh & 7;
    const long rowA = (long)(b * 512 + qbase + w * 16 + r0);
    const long rowB = rowA + 8;
#pragma unroll
    for (int nt = 0; nt < 8; nt++) {
        int col = h * 64 + nt * 8 + c2;
        float v0 = oacc[nt][0] * invA, v1 = oacc[nt][1] * invA;
        float v2 = oacc[nt][2] * invB, v3 = oacc[nt][3] * invB;
        bf16 h0, l0, h1, l1;
        hilo(v0, h0, l0); hilo(v1, h1, l1);
        *(bf162*)(Oh + rowA * 512 + col) = bf162{h0, h1};
        *(bf162*)(Ol + rowA * 512 + col) = bf162{l0, l1};
        hilo(v2, h0, l0); hilo(v3, h1, l1);
        *(bf162*)(Oh + rowB * 512 + col) = bf162{h0, h1};
        *(bf162*)(Ol + rowB * 512 + col) = bf162{l0, l1};
    }
}

// ---------------- reductions ----------------
__device__ __forceinline__ float warpRedMax(float v) {
#pragma unroll
    for (int o = 16; o > 0; o >>= 1) v = fmaxf(v, __shfl_xor_sync(0xffffffffu, v, o));
    return v;
}
__device__ __forceinline__ float warpRedSum(float v) {
#pragma unroll
    for (int o = 16; o > 0; o >>= 1) v += __shfl_xor_sync(0xffffffffu, v, o);
    return v;
}

// ---------------- conversions ----------------
__global__ void trans_hilo(const float* __restrict__ in, bf16* __restrict__ oh,
                           bf16* __restrict__ ol, int Rr, int Cc, long sDst1, long sDst2)
{
    __shared__ float t[32][33];
    int zz = blockIdx.z;
    long sbase = (long)zz * Rr * Cc;
    long dbase = (long)(zz >> 3) * sDst1 + (long)(zz & 7) * sDst2;
    int c0 = blockIdx.x * 32, r0 = blockIdx.y * 32;
    int tx = threadIdx.x, ty = threadIdx.y;
#pragma unroll
    for (int i = 0; i < 32; i += 8)
        t[ty + i][tx] = in[sbase + (long)(r0 + ty + i) * Cc + c0 + tx];
    __syncthreads();
#pragma unroll
    for (int i = 0; i < 32; i += 8) {
        float v = t[tx][ty + i];
        long o = dbase + (long)(c0 + ty + i) * Rr + (r0 + tx);
        bf16 h, l; hilo(v, h, l);
        oh[o] = h; ol[o] = l;
    }
}

__global__ __launch_bounds__(256) void flat_hilo(
    const float* __restrict__ in, bf16* __restrict__ oh, bf16* __restrict__ ol, int n)
{
    int i = blockIdx.x * 256 + threadIdx.x;
    if (i < n) { bf16 h, l; hilo(in[i], h, l); oh[i] = h; ol[i] = l; }
}

// ---------------- embedding + positional ----------------
__global__ __launch_bounds__(256) void embed_kernel(
    const float* __restrict__ embed, const int* __restrict__ dec,
    float* __restrict__ x, bf16* __restrict__ xh, bf16* __restrict__ xl)
{
    int idx = blockIdx.x * 256 + threadIdx.x;
    int r = idx / M_;
    int m = idx - r * M_;
    int c = r & (C_ - 1);
    int tok = dec[r];
    float denom = powf(10000.0f, (float)m / (float)(M_ - 1));
    float arg = (float)c / denom;
    float p = (m & 1) ? cosf(arg) : sinf(arg);
    float v = embed[(size_t)tok * M_ + m] + p;
    x[idx] = v;
    bf16 h, l; hilo(v, h, l);
    xh[idx] = h; xl[idx] = l;
}

// ---------------- x = LN(x + y)*g + b ; emit hi/lo ----------------
__global__ __launch_bounds__(128) void add_ln_kernel(
    float* __restrict__ x, const float* __restrict__ y,
    const float* __restrict__ g, const float* __restrict__ b,
    bf16* __restrict__ xh, bf16* __restrict__ xl)
{
    long row = blockIdx.x;
    float* xr = x + row * M_;
    const float* yr = y + row * M_;
    int t = threadIdx.x;
    float4 a = ((float4*)xr)[t];
    float4 c = ((const float4*)yr)[t];
    float v[4] = {a.x + c.x, a.y + c.y, a.z + c.z, a.w + c.w};
    float ls = v[0] + v[1] + v[2] + v[3];
    ls = warpRedSum(ls);
    __shared__ float r1[4], r2[4];
    int wid = t >> 5, lane = t & 31;
    if (!lane) r1[wid] = ls;
    __syncthreads();
    float mu = (r1[0] + r1[1] + r1[2] + r1[3]) * (1.0f / M_);
    float lq = 0.0f;
#pragma unroll
    for (int j = 0; j < 4; j++) { float d = v[j] - mu; lq += d * d; }
    lq = warpRedSum(lq);
    if (!lane) r2[wid] = lq;
    __syncthreads();
    float var = (r2[0] + r2[1] + r2[2] + r2[3]) * (1.0f / M_);
    float inv = rsqrtf(var + 1e-5f);
    float4 gg = ((const float4*)g)[t];
    float4 bb = ((const float4*)b)[t];
    float o[4];
    o[0] = (v[0] - mu) * inv * gg.x + bb.x;
    o[1] = (v[1] - mu) * inv * gg.y + bb.y;
    o[2] = (v[2] - mu) * inv * gg.z + bb.z;
    o[3] = (v[3] - mu) * inv * gg.w + bb.w;
    float4 of = {o[0], o[1], o[2], o[3]};
    ((float4*)xr)[t] = of;
    long base = row * M_ + (t << 2);
    bf16 h[4], l[4];
#pragma unroll
    for (int j = 0; j < 4; j++) hilo(o[j], h[j], l[j]);
    bf162 H0{h[0],h[1]}, H1{h[2],h[3]}, L0{l[0],l[1]}, L1{l[2],l[3]};
    *(bf162*)(xh + base) = H0; *(bf162*)(xh + base + 2) = H1;
    *(bf162*)(xl + base) = L0; *(bf162*)(xl + base + 2) = L1;
}

// ---------------- final softmax: online pass, then normalize pass ----------------
__global__ __launch_bounds__(512) void softmax_final_kernel(float* __restrict__ out)
{
    long row = blockIdx.x;
    float* p = out + row * (long)T_;
    int t = threadIdx.x;
    float m = -1e30f, s = 0.0f;
    for (int i = t; i < T_; i += 512) {
        float v = p[i];
        if (v > m) { s = s * __expf(m - v) + 1.0f; m = v; }
        else s += __expf(v - m);
    }
#pragma unroll
    for (int o = 16; o > 0; o >>= 1) {
        float m2 = __shfl_xor_sync(0xffffffffu, m, o);
        float s2 = __shfl_xor_sync(0xffffffffu, s, o);
        float M = fmaxf(m, m2);
        s = s * __expf(m - M) + s2 * __expf(m2 - M);
        m = M;
    }
    __shared__ float rm[16], rs[16];
    int wid = t >> 5, lane = t & 31;
    if (!lane) { rm[wid] = m; rs[wid] = s; }
    __syncthreads();
    float M = rm[0], S = rs[0];
#pragma unroll
    for (int j = 1; j < 16; j++) {
        float M2 = fmaxf(M, rm[j]);
        S = S * __expf(M - M2) + rs[j] * __expf(rm[j] - M2);
        M = M2;
    }
    float inv = 1.0f / S;
    for (int i = t; i < T_; i += 512) p[i] = __expf(p[i] - M) * inv;
}

// ---------------- driver ----------------
#define SMEM64   (3 * (2 * 128 * 80 + 2 * 64 * 80))   // 92160,  NS=3, 2 CTA/SM
#define SMEM64_4 (4 * (2 * 128 * 80 + 2 * 64 * 80))   // 122880, NS=4, 1 CTA/SM

extern "C" void kernel_launch(void* const* d_in, const int* in_sizes, int n_in,
                              void* d_out, int out_size)
{
    const float* enc = (const float*)d_in[0];
    const int*   dec = (const int*)d_in[1];
    const float* emb = (const float*)d_in[2];
    const float* wq  = (const float*)d_in[3];
    const float* wk  = (const float*)d_in[4];
    const float* wv  = (const float*)d_in[5];
    const float* wo  = (const float*)d_in[6];
    const float* w1  = (const float*)d_in[7];
    const float* b1  = (const float*)d_in[8];
    const float* w2  = (const float*)d_in[9];
    const float* b2  = (const float*)d_in[10];
    const float* lng = (const float*)d_in[11];
    const float* lnb = (const float*)d_in[12];
    const float* wf  = (const float*)d_in[13];
    const float* bf  = (const float*)d_in[14];
    float* out = (float*)d_out;

    float *px, *ptmp;
    bf16 *pxh, *pxl, *pech, *pecl, *pqh, *pql, *pkh, *pkl, *pvth, *pvtl;
    bf16 *pckh, *pckl, *pcvth, *pcvtl;
    bf16 *pph, *ppl, *pfh, *pfl;
    bf16 *wqkvh, *wqkvl, *woh, *wol, *w1h, *w1l, *w2h, *w2l, *wfh, *wfl;
    cudaGetSymbolAddress((void**)&px, g_x);
    cudaGetSymbolAddress((void**)&ptmp, g_tmp);
    cudaGetSymbolAddress((void**)&pxh, g_xh);   cudaGetSymbolAddress((void**)&pxl, g_xl);
    cudaGetSymbolAddress((void**)&pech, g_ench);cudaGetSymbolAddress((void**)&pecl, g_encl);
    cudaGetSymbolAddress((void**)&pqh, g_qh);   cudaGetSymbolAddress((void**)&pql, g_ql);
    cudaGetSymbolAddress((void**)&pkh, g_kh);   cudaGetSymbolAddress((void**)&pkl, g_kl);
    cudaGetSymbolAddress((void**)&pvth, g_vth); cudaGetSymbolAddress((void**)&pvtl, g_vtl);
    cudaGetSymbolAddress((void**)&pckh, g_ckh); cudaGetSymbolAddress((void**)&pckl, g_ckl);
    cudaGetSymbolAddress((void**)&pcvth, g_cvth); cudaGetSymbolAddress((void**)&pcvtl, g_cvtl);
    cudaGetSymbolAddress((void**)&pph, g_preh); cudaGetSymbolAddress((void**)&ppl, g_prel);
    cudaGetSymbolAddress((void**)&pfh, g_ffh);  cudaGetSymbolAddress((void**)&pfl, g_ffl);
    cudaGetSymbolAddress((void**)&wqkvh, g_wqkv_h); cudaGetSymbolAddress((void**)&wqkvl, g_wqkv_l);
    cudaGetSymbolAddress((void**)&woh, g_wot_h);cudaGetSymbolAddress((void**)&wol, g_wot_l);
    cudaGetSymbolAddress((void**)&w1h, g_w1t_h);cudaGetSymbolAddress((void**)&w1l, g_w1t_l);
    cudaGetSymbolAddress((void**)&w2h, g_w2t_h);cudaGetSymbolAddress((void**)&w2l, g_w2t_l);
    cudaGetSymbolAddress((void**)&wfh, g_wft_h);cudaGetSymbolAddress((void**)&wfl, g_wft_l);

    cudaFuncSetAttribute(tcmm<64,3,2,1,4,false,false>,  cudaFuncAttributeMaxDynamicSharedMemorySize, SMEM64);
    cudaFuncSetAttribute(tcmm<64,3,2,1,5,false,false>,  cudaFuncAttributeMaxDynamicSharedMemorySize, SMEM64);
    cudaFuncSetAttribute(tcmm<64,4,1,1,2,false,false>,  cudaFuncAttributeMaxDynamicSharedMemorySize, SMEM64_4);
    cudaFuncSetAttribute(tcmm<64,4,1,0,0,false,false>,  cudaFuncAttributeMaxDynamicSharedMemorySize, SMEM64_4);
    cudaFuncSetAttribute(tcmm<64,3,2,1,0,true,true>,    cudaFuncAttributeMaxDynamicSharedMemorySize, SMEM64);
    cudaFuncSetAttribute(tcmm<64,4,1,0,0,true,false>,   cudaFuncAttributeMaxDynamicSharedMemorySize, SMEM64_4);
    cudaFuncSetAttribute(tcmm<64,3,2,0,0,true,false>,   cudaFuncAttributeMaxDynamicSharedMemorySize, SMEM64);
    cudaFuncSetAttribute(flash_attn<true>,  cudaFuncAttributeMaxDynamicSharedMemorySize, FSMEM);
    cudaFuncSetAttribute(flash_attn<false>, cudaFuncAttributeMaxDynamicSharedMemorySize, FSMEM);

    const long MM = (long)M_ * M_;
    dim3 blk(32, 8);
    trans_hilo<<<dim3(2, 16, 96), blk>>>(wq, wqkvh,          wqkvl,          512, 64, 3 * MM, 64 * 512);
    trans_hilo<<<dim3(2, 16, 96), blk>>>(wk, wqkvh + MM,     wqkvl + MM,     512, 64, 3 * MM, 64 * 512);
    trans_hilo<<<dim3(2, 16, 96), blk>>>(wv, wqkvh + 2 * MM, wqkvl + 2 * MM, 512, 64, 3 * MM, 64 * 512);
    trans_hilo<<<dim3(16, 16, 12), blk>>>(wo, woh, wol, 512, 512,  8 * MM, MM);
    trans_hilo<<<dim3(64, 16, 6), blk>>>(w1, w1h, w1l, 512, 2048, 8L * 512 * 2048, (long)512 * 2048);
    trans_hilo<<<dim3(16, 64, 6), blk>>>(w2, w2h, w2l, 2048, 512, 8L * 512 * 2048, (long)512 * 2048);
    flat_hilo<<<(T_ * M_) / 256, 256>>>(wf, wfh, wfl, T_ * M_);
    flat_hilo<<<RM / 256, 256>>>(enc, pech, pecl, RM);

    embed_kernel<<<RM / 256, 256>>>(emb, dec, px, pxh, pxl);

    // all 6 layers' cross-attention K|V upfront (block (2l+1), k-section)
    tcmm<64,3,2,1,5,false,false><<<dim3(16, 16, 6), 256, SMEM64>>>(
        pech, pecl, 512, 0, wqkvh + 3 * MM + MM, wqkvl + 3 * MM + MM, 512, 6 * MM, nullptr,
        nullptr, pckh, pckl, pcvth, pcvtl, 0, 0, 512, 512, 0);

    for (int l = 0; l < L_; l++) {
        for (int s = 0; s < 2; s++) {
            long wOff = (long)(l * 2 + s) * 3 * MM;
            long woOff = (long)(l * 2 + s) * MM;

            if (s == 0) {
                tcmm<64,3,2,1,4,false,false><<<dim3(24, 16, 1), 256, SMEM64>>>(
                    pxh, pxl, 512, 0, wqkvh + wOff, wqkvl + wOff, 512, 0, nullptr,
                    nullptr, nullptr, nullptr, nullptr, nullptr, 0, 0, 512, 0, 0);
                flash_attn<true><<<dim3(4, 32), 256, FSMEM>>>(
                    pqh, pql, pkh, pkl, pvth, pvtl, pph, ppl);
            } else {
                // 128-CTA launch: NS=4 deep pipeline (no co-residency possible)
                tcmm<64,4,1,1,2,false,false><<<dim3(8, 16, 1), 256, SMEM64_4>>>(
                    pxh, pxl, 512, 0, wqkvh + wOff, wqkvl + wOff, 512, 0, nullptr,
                    nullptr, pqh, pql, nullptr, nullptr, 0, 0, 512, 0, 0);
                flash_attn<false><<<dim3(4, 32), 256, FSMEM>>>(
                    pqh, pql, pckh + (long)l * RM, pckl + (long)l * RM,
                    pcvth + (long)l * RM, pcvtl + (long)l * RM, pph, ppl);
            }

            tcmm<64,4,1,0,0,false,false><<<dim3(8, 16, 1), 256, SMEM64_4>>>(
                pph, ppl, 512, 0, woh + woOff, wol + woOff, 512, 0, nullptr,
                ptmp, nullptr, nullptr, nullptr, nullptr, 512, 0, 512, 0, 0);

            add_ln_kernel<<<R_, 128>>>(px, ptmp,
                lng + (size_t)(l * 3 + s) * M_, lnb + (size_t)(l * 3 + s) * M_, pxh, pxl);
        }
        long w1Off = (long)l * M_ * F_;
        tcmm<64,3,2,1,0,true,true><<<dim3(32, 16, 1), 256, SMEM64>>>(
            pxh, pxl, 512, 0, w1h + w1Off, w1l + w1Off, 512, 0, b1 + (size_t)l * F_,
            nullptr, pfh, pfl, nullptr, nullptr, 2048, 0, 512, 0, 0);
        tcmm<64,4,1,0,0,true,false><<<dim3(8, 16, 1), 256, SMEM64_4>>>(
            pfh, pfl, 2048, 0, w2h + w1Off, w2l + w1Off, 2048, 0, b2 + (size_t)l * M_,
            ptmp, nullptr, nullptr, nullptr, nullptr, 512, 0, 2048, 0, 0);
        add_ln_kernel<<<R_, 128>>>(px, ptmp,
            lng + (size_t)(l * 3 + 2) * M_, lnb + (size_t)(l * 3 + 2) * M_, pxh, pxl);
    }

    // vocab projection: BN=64, 2 CTA/SM, swapped grid (weight-tile sharers adjacent)
    tcmm<64,3,2,0,0,true,false><<<dim3(16, 500, 1), 256, SMEM64>>>(
        pxh, pxl, 512, 0, wfh, wfl, 512, 0, bf,
        out, nullptr, nullptr, nullptr, nullptr, 32000, 0, 512, 0, 1);
    softmax_final_kernel<<<R_, 512>>>(out);
}